// round 14
// baseline (speedup 1.0000x reference)
#include <cuda_runtime.h>
#include <cuda_fp16.h>
#include <cstdint>

#define HID 128
#define NMAX 100000
#define CAP 32
#define WS_STRIDE 144   // 144 mod 32 == 16 -> conflict-free LDS.128 phases
#define NCTA 296        // 2 CTAs/SM x 148 SMs (smem 73.7 KB/CTA)

// scratch (no cudaMalloc allowed). g_cnt zero at module load; k_fused
// re-zeroes it every run so each execution starts from zeroed counters.
static __device__ __half g_h[(size_t)2 * NMAX * HID];    // 51.2 MB (S,I fp16)
static __device__ int    g_cnt[NMAX];
static __device__ int    g_csr[(size_t)NMAX * CAP];      // 12.8 MB

__device__ __forceinline__ float to_tf32(float x) {
    unsigned u;
    asm("cvt.rna.tf32.f32 %0, %1;" : "=r"(u) : "f"(x));
    return __uint_as_float(u);
}

__device__ __forceinline__ void mma_tf32(float* acc, unsigned a0, unsigned a1,
                                         unsigned a2, unsigned a3,
                                         unsigned b0, unsigned b1) {
    asm volatile(
        "mma.sync.aligned.m16n8k8.row.col.f32.tf32.tf32.f32 "
        "{%0,%1,%2,%3}, {%4,%5,%6,%7}, {%8,%9}, {%0,%1,%2,%3};"
        : "+f"(acc[0]), "+f"(acc[1]), "+f"(acc[2]), "+f"(acc[3])
        : "r"(a0), "r"(a1), "r"(a2), "r"(a3), "r"(b0), "r"(b1));
}

// Persistent GEMM + edge fill. CTA tile 128x128, warp tile 32x64 (W-smem
// traffic amortized over 2x A-rows). A frags direct from gmem (raw f32 bits
// -> tf32 MMA HW truncation); W staged once (RNA tf32). h stored fp16.
__global__ __launch_bounds__(256, 2) void k_gemm_fill(
    const float* __restrict__ A, const float* __restrict__ W,
    const float* __restrict__ bias, int M,
    const int* __restrict__ er, const int* __restrict__ ec, int E, int n) {
    extern __shared__ float Ws[];   // 128 x WS_STRIDE tf32, 73.7 KB
    int tid = threadIdx.x;
    int bid = blockIdx.x;

    // --- edge fill slice ---
    for (int e = bid * 256 + tid; e < E; e += NCTA * 256) {
        int r = er[e];
        int c = ec[e];
        if ((unsigned)r < (unsigned)n && (unsigned)c < (unsigned)n) {
            int pos = atomicAdd(&g_cnt[r], 1) & (CAP - 1);
            g_csr[(size_t)r * CAP + pos] = c;
        }
    }

    // --- stage W once (RNA tf32) ---
    for (int i = tid; i < 128 * 32; i += 256) {
        int r = i >> 5, q = i & 31;
        float4 v = *(const float4*)(W + r * HID + q * 4);
        *(float4*)(Ws + r * WS_STRIDE + q * 4) =
            make_float4(to_tf32(v.x), to_tf32(v.y), to_tf32(v.z), to_tf32(v.w));
    }
    __syncthreads();

    int w = tid >> 5, lane = tid & 31;
    int gid = lane >> 2, tig = lane & 3;
    int rw = w >> 1;            // row-warp 0..3 -> rows rw*32..rw*32+31
    int ch = w & 1;             // col half 0..1
    const float* Wb = Ws + (ch * 64) * WS_STRIDE;

    int ntiles = (M + 127) >> 7;   // 128-row tiles (last one partial)
    for (int t = bid; t < ntiles; t += NCTA) {
        int row = t * 128 + rw * 32 + gid;     // + {0,8,16,24}
        const float4* A0p = (const float4*)(A + (size_t)row * HID);
        const float4* A1p = (const float4*)(A + (size_t)(row + 8) * HID);
        const float4* A2p = (const float4*)(A + (size_t)(row + 16) * HID);
        const float4* A3p = (const float4*)(A + (size_t)(row + 24) * HID);

        float acc[8][2][4];
#pragma unroll
        for (int nt = 0; nt < 8; nt++)
#pragma unroll
            for (int p = 0; p < 2; p++)
                acc[nt][p][0] = acc[nt][p][1] = acc[nt][p][2] = acc[nt][p][3] = 0.f;

        // rows beyond M read into I/R region of x — finite garbage, never stored
#pragma unroll
        for (int c8 = 0; c8 < 8; c8++) {
            float4 a0 = A0p[c8 * 4 + tig];
            float4 a1 = A1p[c8 * 4 + tig];
            float4 a2 = A2p[c8 * 4 + tig];
            float4 a3 = A3p[c8 * 4 + tig];
            unsigned a0x = __float_as_uint(a0.x), a0y = __float_as_uint(a0.y);
            unsigned a0z = __float_as_uint(a0.z), a0w = __float_as_uint(a0.w);
            unsigned a1x = __float_as_uint(a1.x), a1y = __float_as_uint(a1.y);
            unsigned a1z = __float_as_uint(a1.z), a1w = __float_as_uint(a1.w);
            unsigned a2x = __float_as_uint(a2.x), a2y = __float_as_uint(a2.y);
            unsigned a2z = __float_as_uint(a2.z), a2w = __float_as_uint(a2.w);
            unsigned a3x = __float_as_uint(a3.x), a3y = __float_as_uint(a3.y);
            unsigned a3z = __float_as_uint(a3.z), a3w = __float_as_uint(a3.w);
#pragma unroll
            for (int nt = 0; nt < 8; nt++) {
                float4 w4 = *(const float4*)(Wb + (nt * 8 + gid) * WS_STRIDE + c8 * 16 + 4 * tig);
                unsigned wx = __float_as_uint(w4.x), wy = __float_as_uint(w4.y);
                unsigned wz = __float_as_uint(w4.z), ww = __float_as_uint(w4.w);
                mma_tf32(acc[nt][0], a0x, a1x, a0y, a1y, wx, wy);
                mma_tf32(acc[nt][0], a0z, a1z, a0w, a1w, wz, ww);
                mma_tf32(acc[nt][1], a2x, a3x, a2y, a3y, wx, wy);
                mma_tf32(acc[nt][1], a2z, a3z, a2w, a3w, wz, ww);
            }
        }

#pragma unroll
        for (int nt = 0; nt < 8; nt++) {
            int col = ch * 64 + nt * 8 + tig * 2;
            float bc0 = __ldg(bias + col), bc1 = __ldg(bias + col + 1);
#pragma unroll
            for (int p = 0; p < 2; p++) {
                int r0 = row + p * 16;
                if (r0 < M)
                    *(__half2*)(g_h + (size_t)r0 * HID + col) =
                        __floats2half2_rn(fmaxf(acc[nt][p][0] + bc0, 0.f),
                                          fmaxf(acc[nt][p][1] + bc1, 0.f));
                if (r0 + 8 < M)
                    *(__half2*)(g_h + (size_t)(r0 + 8) * HID + col) =
                        __floats2half2_rn(fmaxf(acc[nt][p][2] + bc0, 0.f),
                                          fmaxf(acc[nt][p][3] + bc1, 0.f));
            }
        }
    }
}

__device__ __forceinline__ float4 ln_apply(float4 v, float m, float rinv,
                                           float4 lw, float4 lb) {
    return make_float4((v.x - m) * rinv * lw.x + lb.x,
                       (v.y - m) * rinv * lw.y + lb.y,
                       (v.z - m) * rinv * lw.z + lb.z,
                       (v.w - m) * rinv * lw.w + lb.w);
}

__device__ __forceinline__ float4 h_to_f4(uint2 u) {
    float2 a = __half22float2(*(__half2*)&u.x);
    float2 b = __half22float2(*(__half2*)&u.y);
    return make_float4(a.x, a.y, b.x, b.y);
}

// One warp per node: fp16 S/I/gather (half the memory traffic), f32 math,
// 3x LN (six interleaved moment reductions), tail copy. Resets g_cnt.
__global__ __launch_bounds__(256) void k_fused(
    const float* __restrict__ x, const float* __restrict__ lnw,
    const float* __restrict__ lnb, float* __restrict__ out, int n) {
    int warp = threadIdx.x >> 5, lane = threadIdx.x & 31;
    int i = blockIdx.x * 8 + warp;
    if (i >= n) return;

    const uint2*  h2v = (const uint2*)g_h;     // 32 x uint2 (4 halves) per row
    const float4* x4 = (const float4*)x;
    float4* o4 = (float4*)out;

    float4 S = h_to_f4(__ldcs(&h2v[(size_t)i * 32 + lane]));
    float4 I = h_to_f4(h2v[((size_t)n + i) * 32 + lane]);
    float4 X = __ldcs(&x4[((size_t)3 * n + i) * 32 + lane]);
    float beta = __shfl_sync(0xffffffffu, X.x, 0);
    float gam  = __shfl_sync(0xffffffffu, X.y, 0);

    int deg = min(g_cnt[i], CAP);
    if (lane == 0) g_cnt[i] = 0;                 // restore invariant for next run
    int c = (lane < deg) ? g_csr[(size_t)i * CAP + lane] : 0;

    float4 A0 = make_float4(0.f, 0.f, 0.f, 0.f);
    float4 A1 = make_float4(0.f, 0.f, 0.f, 0.f);
    int j = 0;
    for (; j + 2 <= deg; j += 2) {
        int c0 = __shfl_sync(0xffffffffu, c, j);
        int c1 = __shfl_sync(0xffffffffu, c, j + 1);
        float4 v0 = h_to_f4(h2v[((size_t)n + c0) * 32 + lane]);
        float4 v1 = h_to_f4(h2v[((size_t)n + c1) * 32 + lane]);
        A0.x += v0.x; A0.y += v0.y; A0.z += v0.z; A0.w += v0.w;
        A1.x += v1.x; A1.y += v1.y; A1.z += v1.z; A1.w += v1.w;
    }
    if (j < deg) {
        int c0 = __shfl_sync(0xffffffffu, c, j);
        float4 v0 = h_to_f4(h2v[((size_t)n + c0) * 32 + lane]);
        A0.x += v0.x; A0.y += v0.y; A0.z += v0.z; A0.w += v0.w;
    }
    float4 AI = make_float4(A0.x + A1.x, A0.y + A1.y, A0.z + A1.z, A0.w + A1.w);

    float4 dS = make_float4(-beta * AI.x * S.x, -beta * AI.y * S.y,
                            -beta * AI.z * S.z, -beta * AI.w * S.w);
    float4 dI = make_float4(-dS.x - gam * I.x, -dS.y - gam * I.y,
                            -dS.z - gam * I.z, -dS.w - gam * I.w);
    float4 dR = make_float4(gam * I.x, gam * I.y, gam * I.z, gam * I.w);

    float sa1 = (dS.x + dS.y) + (dS.z + dS.w);
    float sa2 = (dS.x * dS.x + dS.y * dS.y) + (dS.z * dS.z + dS.w * dS.w);
    float sb1 = (dI.x + dI.y) + (dI.z + dI.w);
    float sb2 = (dI.x * dI.x + dI.y * dI.y) + (dI.z * dI.z + dI.w * dI.w);
    float sc1 = (dR.x + dR.y) + (dR.z + dR.w);
    float sc2 = (dR.x * dR.x + dR.y * dR.y) + (dR.z * dR.z + dR.w * dR.w);
#pragma unroll
    for (int o = 16; o; o >>= 1) {
        sa1 += __shfl_xor_sync(0xffffffffu, sa1, o);
        sa2 += __shfl_xor_sync(0xffffffffu, sa2, o);
        sb1 += __shfl_xor_sync(0xffffffffu, sb1, o);
        sb2 += __shfl_xor_sync(0xffffffffu, sb2, o);
        sc1 += __shfl_xor_sync(0xffffffffu, sc1, o);
        sc2 += __shfl_xor_sync(0xffffffffu, sc2, o);
    }
    float ma = sa1 * (1.f / 128.f), mb = sb1 * (1.f / 128.f), mc = sc1 * (1.f / 128.f);
    float ra = rsqrtf(fmaxf(sa2 * (1.f / 128.f) - ma * ma, 0.f) + 1e-5f);
    float rb = rsqrtf(fmaxf(sb2 * (1.f / 128.f) - mb * mb, 0.f) + 1e-5f);
    float rc = rsqrtf(fmaxf(sc2 * (1.f / 128.f) - mc * mc, 0.f) + 1e-5f);

    float4 lw = __ldg((const float4*)lnw + lane);
    float4 lb = __ldg((const float4*)lnb + lane);

    __stcs(&o4[(size_t)i * 32 + lane],           ln_apply(dS, ma, ra, lw, lb));
    __stcs(&o4[((size_t)n + i) * 32 + lane],     ln_apply(dI, mb, rb, lw, lb));
    __stcs(&o4[((size_t)2 * n + i) * 32 + lane], ln_apply(dR, mc, rc, lw, lb));
    __stcs(&o4[((size_t)3 * n + i) * 32 + lane], X);
}

extern "C" void kernel_launch(void* const* d_in, const int* in_sizes, int n_in,
                              void* d_out, int out_size) {
    // inputs: t, x, edge_row, edge_col, W, b, ln_w, ln_b (t unused)
    const float* x   = (const float*)d_in[1];
    const int*   er  = (const int*)d_in[2];
    const int*   ec  = (const int*)d_in[3];
    const float* W   = (const float*)d_in[4];
    const float* b   = (const float*)d_in[5];
    const float* lnw = (const float*)d_in[6];
    const float* lnb = (const float*)d_in[7];
    float* out = (float*)d_out;

    int n = (in_sizes[1] / HID) / 4;
    int E = in_sizes[2];
    int M = 2 * n;  // only S and I rows of h are ever used

    const int SMEM = 128 * WS_STRIDE * 4;
    cudaFuncSetAttribute(k_gemm_fill, cudaFuncAttributeMaxDynamicSharedMemorySize, SMEM);
    k_gemm_fill<<<NCTA, 256, SMEM>>>(x, W, b, M, er, ec, E, n);

    k_fused<<<(n + 7) / 8, 256>>>(x, lnw, lnb, out, n);
}

// round 15
// speedup vs baseline: 1.2599x; 1.2599x over previous
#include <cuda_runtime.h>
#include <cuda_fp16.h>
#include <cstdint>

#define HID 128
#define NMAX 100000
#define CAP 32
#define WSH 144         // W smem stride in halves (288 B) -> half-warp conflict-free LDS.64
#define NCTA 296        // 2 CTAs/SM x 148 SMs

// scratch (no cudaMalloc allowed). g_cnt zero at module load; k_fused
// re-zeroes it every run so each execution starts from zeroed counters.
static __device__ float g_h[(size_t)2 * NMAX * HID];     // 102.4 MB (S,I f32)
static __device__ int   g_cnt[NMAX];
static __device__ int   g_csr[(size_t)NMAX * CAP];       // 12.8 MB

__device__ __forceinline__ unsigned f2h2(float x, float y) {
    __half2 h = __floats2half2_rn(x, y);
    return *(unsigned*)&h;
}

// m16n8k16 fp16 MMA, f32 accum
__device__ __forceinline__ void mma_f16(float* acc, unsigned a0, unsigned a1,
                                        unsigned a2, unsigned a3,
                                        unsigned b0, unsigned b1) {
    asm volatile(
        "mma.sync.aligned.m16n8k16.row.col.f32.f16.f16.f32 "
        "{%0,%1,%2,%3}, {%4,%5,%6,%7}, {%8,%9}, {%0,%1,%2,%3};"
        : "+f"(acc[0]), "+f"(acc[1]), "+f"(acc[2]), "+f"(acc[3])
        : "r"(a0), "r"(a1), "r"(a2), "r"(a3), "r"(b0), "r"(b1));
}

// Persistent GEMM + edge fill. CTA tile 128x128, warp tile 32x64.
// fp16 m16n8k16 MMA (same 10-bit mantissa as tf32; inputs N(0,1) -> range
// safe). W staged once in smem as fp16 (stride 144 halves, conflict-free).
// A: float4 from gmem -> cvt.rn.f16x2 packs. k-permutation: MMA k-slots
// (2t,2t+1)&(2t+8,2t+9) carry actual k = k0+4t..+3 for BOTH A and B.
// h written f32 (k_fused is latency-structured; f32 loads measured faster).
__global__ __launch_bounds__(256, 2) void k_gemm_fill(
    const float* __restrict__ A, const float* __restrict__ W,
    const float* __restrict__ bias, int M,
    const int* __restrict__ er, const int* __restrict__ ec, int E, int n) {
    extern __shared__ __half Ws[];   // 128 x WSH halves = 36.9 KB
    int tid = threadIdx.x;
    int bid = blockIdx.x;

    // --- edge fill slice (~7 edges/thread, overlapped with staging) ---
    for (int e = bid * 256 + tid; e < E; e += NCTA * 256) {
        int r = er[e];
        int c = ec[e];
        if ((unsigned)r < (unsigned)n && (unsigned)c < (unsigned)n) {
            int pos = atomicAdd(&g_cnt[r], 1) & (CAP - 1);
            g_csr[(size_t)r * CAP + pos] = c;
        }
    }

    // --- stage W once as fp16 ---
    for (int i = tid; i < 128 * 32; i += 256) {
        int r = i >> 5, s = i & 31;                    // s = half4 granule
        float4 v = *(const float4*)(W + r * HID + s * 4);
        uint2 u = make_uint2(f2h2(v.x, v.y), f2h2(v.z, v.w));
        *(uint2*)(Ws + r * WSH + s * 4) = u;
    }
    __syncthreads();

    int w = tid >> 5, lane = tid & 31;
    int gid = lane >> 2, tig = lane & 3;
    int rw = w >> 1;            // row-warp 0..3 -> rows rw*32..rw*32+31
    int ch = w & 1;             // col half 0..1
    const __half* Wb = Ws + (ch * 64) * WSH;

    int ntiles = (M + 127) >> 7;   // 128-row tiles (last one partial)
    for (int t = bid; t < ntiles; t += NCTA) {
        int row = t * 128 + rw * 32 + gid;     // + {0,8,16,24}
        const float4* A0p = (const float4*)(A + (size_t)row * HID);
        const float4* A1p = (const float4*)(A + (size_t)(row + 8) * HID);
        const float4* A2p = (const float4*)(A + (size_t)(row + 16) * HID);
        const float4* A3p = (const float4*)(A + (size_t)(row + 24) * HID);

        float acc[8][2][4];
#pragma unroll
        for (int nt = 0; nt < 8; nt++)
#pragma unroll
            for (int p = 0; p < 2; p++)
                acc[nt][p][0] = acc[nt][p][1] = acc[nt][p][2] = acc[nt][p][3] = 0.f;

        // rows beyond M read into I/R region of x — finite garbage, never stored
#pragma unroll
        for (int c16 = 0; c16 < 8; c16++) {          // k chunk of 16
            float4 v0 = A0p[c16 * 4 + tig];
            float4 v1 = A1p[c16 * 4 + tig];
            float4 v2 = A2p[c16 * 4 + tig];
            float4 v3 = A3p[c16 * 4 + tig];
            // p0: rows gid / gid+8 ; p1: rows gid+16 / gid+24
            unsigned a00 = f2h2(v0.x, v0.y), a02 = f2h2(v0.z, v0.w);
            unsigned a01 = f2h2(v1.x, v1.y), a03 = f2h2(v1.z, v1.w);
            unsigned a10 = f2h2(v2.x, v2.y), a12 = f2h2(v2.z, v2.w);
            unsigned a11 = f2h2(v3.x, v3.y), a13 = f2h2(v3.z, v3.w);
#pragma unroll
            for (int nt = 0; nt < 8; nt++) {
                uint2 wv = *(const uint2*)(Wb + (nt * 8 + gid) * WSH + c16 * 16 + tig * 4);
                mma_f16(acc[nt][0], a00, a01, a02, a03, wv.x, wv.y);
                mma_f16(acc[nt][1], a10, a11, a12, a13, wv.x, wv.y);
            }
        }

#pragma unroll
        for (int nt = 0; nt < 8; nt++) {
            int col = ch * 64 + nt * 8 + tig * 2;
            float bc0 = __ldg(bias + col), bc1 = __ldg(bias + col + 1);
#pragma unroll
            for (int p = 0; p < 2; p++) {
                int r0 = row + p * 16;
                if (r0 < M) {
                    g_h[(size_t)r0 * HID + col]     = fmaxf(acc[nt][p][0] + bc0, 0.f);
                    g_h[(size_t)r0 * HID + col + 1] = fmaxf(acc[nt][p][1] + bc1, 0.f);
                }
                if (r0 + 8 < M) {
                    g_h[(size_t)(r0 + 8) * HID + col]     = fmaxf(acc[nt][p][2] + bc0, 0.f);
                    g_h[(size_t)(r0 + 8) * HID + col + 1] = fmaxf(acc[nt][p][3] + bc1, 0.f);
                }
            }
        }
    }
}

__device__ __forceinline__ float4 ln_apply(float4 v, float m, float rinv,
                                           float4 lw, float4 lb) {
    return make_float4((v.x - m) * rinv * lw.x + lb.x,
                       (v.y - m) * rinv * lw.y + lb.y,
                       (v.z - m) * rinv * lw.z + lb.z,
                       (v.w - m) * rinv * lw.w + lb.w);
}

// One warp per node: f32 gather (unroll-2), SIR dynamics, 3x LN with six
// interleaved moment reductions, tail copy. Resets g_cnt for next run.
__global__ __launch_bounds__(256) void k_fused(
    const float* __restrict__ x, const float* __restrict__ lnw,
    const float* __restrict__ lnb, float* __restrict__ out, int n) {
    int warp = threadIdx.x >> 5, lane = threadIdx.x & 31;
    int i = blockIdx.x * 8 + warp;
    if (i >= n) return;

    const float4* h4 = (const float4*)g_h;
    const float4* x4 = (const float4*)x;
    float4* o4 = (float4*)out;

    float4 S = __ldcs(&h4[(size_t)i * 32 + lane]);
    float4 I = h4[((size_t)n + i) * 32 + lane];
    float4 X = __ldcs(&x4[((size_t)3 * n + i) * 32 + lane]);
    float beta = __shfl_sync(0xffffffffu, X.x, 0);
    float gam  = __shfl_sync(0xffffffffu, X.y, 0);

    int deg = min(g_cnt[i], CAP);
    if (lane == 0) g_cnt[i] = 0;                 // restore invariant for next run
    int c = (lane < deg) ? g_csr[(size_t)i * CAP + lane] : 0;

    float4 A0 = make_float4(0.f, 0.f, 0.f, 0.f);
    float4 A1 = make_float4(0.f, 0.f, 0.f, 0.f);
    int j = 0;
    for (; j + 2 <= deg; j += 2) {
        int c0 = __shfl_sync(0xffffffffu, c, j);
        int c1 = __shfl_sync(0xffffffffu, c, j + 1);
        float4 v0 = h4[((size_t)n + c0) * 32 + lane];
        float4 v1 = h4[((size_t)n + c1) * 32 + lane];
        A0.x += v0.x; A0.y += v0.y; A0.z += v0.z; A0.w += v0.w;
        A1.x += v1.x; A1.y += v1.y; A1.z += v1.z; A1.w += v1.w;
    }
    if (j < deg) {
        int c0 = __shfl_sync(0xffffffffu, c, j);
        float4 v0 = h4[((size_t)n + c0) * 32 + lane];
        A0.x += v0.x; A0.y += v0.y; A0.z += v0.z; A0.w += v0.w;
    }
    float4 AI = make_float4(A0.x + A1.x, A0.y + A1.y, A0.z + A1.z, A0.w + A1.w);

    float4 dS = make_float4(-beta * AI.x * S.x, -beta * AI.y * S.y,
                            -beta * AI.z * S.z, -beta * AI.w * S.w);
    float4 dI = make_float4(-dS.x - gam * I.x, -dS.y - gam * I.y,
                            -dS.z - gam * I.z, -dS.w - gam * I.w);
    float4 dR = make_float4(gam * I.x, gam * I.y, gam * I.z, gam * I.w);

    float sa1 = (dS.x + dS.y) + (dS.z + dS.w);
    float sa2 = (dS.x * dS.x + dS.y * dS.y) + (dS.z * dS.z + dS.w * dS.w);
    float sb1 = (dI.x + dI.y) + (dI.z + dI.w);
    float sb2 = (dI.x * dI.x + dI.y * dI.y) + (dI.z * dI.z + dI.w * dI.w);
    float sc1 = (dR.x + dR.y) + (dR.z + dR.w);
    float sc2 = (dR.x * dR.x + dR.y * dR.y) + (dR.z * dR.z + dR.w * dR.w);
#pragma unroll
    for (int o = 16; o; o >>= 1) {
        sa1 += __shfl_xor_sync(0xffffffffu, sa1, o);
        sa2 += __shfl_xor_sync(0xffffffffu, sa2, o);
        sb1 += __shfl_xor_sync(0xffffffffu, sb1, o);
        sb2 += __shfl_xor_sync(0xffffffffu, sb2, o);
        sc1 += __shfl_xor_sync(0xffffffffu, sc1, o);
        sc2 += __shfl_xor_sync(0xffffffffu, sc2, o);
    }
    float ma = sa1 * (1.f / 128.f), mb = sb1 * (1.f / 128.f), mc = sc1 * (1.f / 128.f);
    float ra = rsqrtf(fmaxf(sa2 * (1.f / 128.f) - ma * ma, 0.f) + 1e-5f);
    float rb = rsqrtf(fmaxf(sb2 * (1.f / 128.f) - mb * mb, 0.f) + 1e-5f);
    float rc = rsqrtf(fmaxf(sc2 * (1.f / 128.f) - mc * mc, 0.f) + 1e-5f);

    float4 lw = __ldg((const float4*)lnw + lane);
    float4 lb = __ldg((const float4*)lnb + lane);

    __stcs(&o4[(size_t)i * 32 + lane],           ln_apply(dS, ma, ra, lw, lb));
    __stcs(&o4[((size_t)n + i) * 32 + lane],     ln_apply(dI, mb, rb, lw, lb));
    __stcs(&o4[((size_t)2 * n + i) * 32 + lane], ln_apply(dR, mc, rc, lw, lb));
    __stcs(&o4[((size_t)3 * n + i) * 32 + lane], X);
}

extern "C" void kernel_launch(void* const* d_in, const int* in_sizes, int n_in,
                              void* d_out, int out_size) {
    // inputs: t, x, edge_row, edge_col, W, b, ln_w, ln_b (t unused)
    const float* x   = (const float*)d_in[1];
    const int*   er  = (const int*)d_in[2];
    const int*   ec  = (const int*)d_in[3];
    const float* W   = (const float*)d_in[4];
    const float* b   = (const float*)d_in[5];
    const float* lnw = (const float*)d_in[6];
    const float* lnb = (const float*)d_in[7];
    float* out = (float*)d_out;

    int n = (in_sizes[1] / HID) / 4;
    int E = in_sizes[2];
    int M = 2 * n;  // only S and I rows of h are ever used

    const int SMEM = 128 * WSH * 2;   // 36.9 KB fp16 W
    cudaFuncSetAttribute(k_gemm_fill, cudaFuncAttributeMaxDynamicSharedMemorySize, SMEM);
    k_gemm_fill<<<NCTA, 256, SMEM>>>(x, W, b, M, er, ec, E, n);

    k_fused<<<(n + 7) / 8, 256>>>(x, lnw, lnb, out, n);
}

// round 16
// speedup vs baseline: 1.3165x; 1.0449x over previous
#include <cuda_runtime.h>
#include <cuda_fp16.h>
#include <cstdint>

#define HID 128
#define NMAX 100000
#define CAP 32
#define WSH 144         // W smem stride in halves (288 B) -> conflict-free
#define NCTA 444        // 3 CTAs/SM x 148 SMs (EVEN: col-half fixed per CTA)

// scratch (no cudaMalloc allowed). g_cnt zero at module load; k_fused
// re-zeroes it every run so each execution starts from zeroed counters.
static __device__ float g_h[(size_t)2 * NMAX * HID];     // 102.4 MB (S,I f32)
static __device__ int   g_cnt[NMAX];
static __device__ int   g_csr[(size_t)NMAX * CAP];       // 12.8 MB

__device__ __forceinline__ unsigned f2h2(float x, float y) {
    __half2 h = __floats2half2_rn(x, y);
    return *(unsigned*)&h;
}

// m16n8k16 fp16 MMA, f32 accum
__device__ __forceinline__ void mma_f16(float* acc, unsigned a0, unsigned a1,
                                        unsigned a2, unsigned a3,
                                        unsigned b0, unsigned b1) {
    asm volatile(
        "mma.sync.aligned.m16n8k16.row.col.f32.f16.f16.f32 "
        "{%0,%1,%2,%3}, {%4,%5,%6,%7}, {%8,%9}, {%0,%1,%2,%3};"
        : "+f"(acc[0]), "+f"(acc[1]), "+f"(acc[2]), "+f"(acc[3])
        : "r"(a0), "r"(a1), "r"(a2), "r"(a3), "r"(b0), "r"(b1));
}

// Persistent GEMM + edge fill. Work unit = 128 rows x 64 cols; warp tile
// 32x32 (acc 32 regs -> 3 CTAs/SM = 24 warps/SM for latency hiding).
// Unit u: t=u>>1 (row tile), chh=u&1 (col half). NCTA even => chh is fixed
// per CTA => W half staged ONCE. Paired units (2t,2t+1) run on adjacent
// CTAs concurrently => A re-read hits L2. fp16 MMA (mantissa == tf32).
__global__ __launch_bounds__(256, 3) void k_gemm_fill(
    const float* __restrict__ A, const float* __restrict__ W,
    const float* __restrict__ bias, int M,
    const int* __restrict__ er, const int* __restrict__ ec, int E, int n) {
    extern __shared__ __half Ws[];   // 64 x WSH halves = 18.4 KB
    int tid = threadIdx.x;
    int bid = blockIdx.x;
    int chh = bid & 1;               // this CTA's col half (fixed)

    // --- edge fill slice (~7 edges/thread, overlapped with staging) ---
    for (int e = bid * 256 + tid; e < E; e += NCTA * 256) {
        int r = er[e];
        int c = ec[e];
        if ((unsigned)r < (unsigned)n && (unsigned)c < (unsigned)n) {
            int pos = atomicAdd(&g_cnt[r], 1) & (CAP - 1);
            g_csr[(size_t)r * CAP + pos] = c;
        }
    }

    // --- stage this CTA's W half (64 rows) as fp16 ---
    for (int i = tid; i < 64 * 32; i += 256) {
        int r = i >> 5, s = i & 31;
        float4 v = *(const float4*)(W + (chh * 64 + r) * HID + s * 4);
        *(uint2*)(Ws + r * WSH + s * 4) = make_uint2(f2h2(v.x, v.y), f2h2(v.z, v.w));
    }
    __syncthreads();

    int w = tid >> 5, lane = tid & 31;
    int gid = lane >> 2, tig = lane & 3;
    int rw = w >> 1;            // row-warp 0..3 -> rows rw*32..+31
    int cw = w & 1;             // col warp 0..1 -> cols cw*32..+31 (in half)
    const __half* Wb = Ws + (cw * 32) * WSH;

    int ntiles = (M + 127) >> 7;
    for (int u = bid; u < 2 * ntiles; u += NCTA) {
        int t = u >> 1;                        // (u&1)==chh by construction
        int row = t * 128 + rw * 32 + gid;     // + {0,8,16,24}
        const float4* A0p = (const float4*)(A + (size_t)row * HID);
        const float4* A1p = (const float4*)(A + (size_t)(row + 8) * HID);
        const float4* A2p = (const float4*)(A + (size_t)(row + 16) * HID);
        const float4* A3p = (const float4*)(A + (size_t)(row + 24) * HID);

        float acc[4][2][4];
#pragma unroll
        for (int nt = 0; nt < 4; nt++)
#pragma unroll
            for (int p = 0; p < 2; p++)
                acc[nt][p][0] = acc[nt][p][1] = acc[nt][p][2] = acc[nt][p][3] = 0.f;

        // rows beyond M read into R region of x — finite garbage, never stored
#pragma unroll
        for (int c16 = 0; c16 < 8; c16++) {
            float4 v0 = A0p[c16 * 4 + tig];
            float4 v1 = A1p[c16 * 4 + tig];
            float4 v2 = A2p[c16 * 4 + tig];
            float4 v3 = A3p[c16 * 4 + tig];
            unsigned a00 = f2h2(v0.x, v0.y), a02 = f2h2(v0.z, v0.w);
            unsigned a01 = f2h2(v1.x, v1.y), a03 = f2h2(v1.z, v1.w);
            unsigned a10 = f2h2(v2.x, v2.y), a12 = f2h2(v2.z, v2.w);
            unsigned a11 = f2h2(v3.x, v3.y), a13 = f2h2(v3.z, v3.w);
#pragma unroll
            for (int nt = 0; nt < 4; nt++) {
                uint2 wv = *(const uint2*)(Wb + (nt * 8 + gid) * WSH + c16 * 16 + tig * 4);
                mma_f16(acc[nt][0], a00, a01, a02, a03, wv.x, wv.y);
                mma_f16(acc[nt][1], a10, a11, a12, a13, wv.x, wv.y);
            }
        }

#pragma unroll
        for (int nt = 0; nt < 4; nt++) {
            int col = chh * 64 + cw * 32 + nt * 8 + tig * 2;
            float bc0 = __ldg(bias + col), bc1 = __ldg(bias + col + 1);
#pragma unroll
            for (int p = 0; p < 2; p++) {
                int r0 = row + p * 16;
                if (r0 < M)
                    *(float2*)(g_h + (size_t)r0 * HID + col) =
                        make_float2(fmaxf(acc[nt][p][0] + bc0, 0.f),
                                    fmaxf(acc[nt][p][1] + bc1, 0.f));
                if (r0 + 8 < M)
                    *(float2*)(g_h + (size_t)(r0 + 8) * HID + col) =
                        make_float2(fmaxf(acc[nt][p][2] + bc0, 0.f),
                                    fmaxf(acc[nt][p][3] + bc1, 0.f));
            }
        }
    }
}

__device__ __forceinline__ float4 ln_apply(float4 v, float m, float rinv,
                                           float4 lw, float4 lb) {
    return make_float4((v.x - m) * rinv * lw.x + lb.x,
                       (v.y - m) * rinv * lw.y + lb.y,
                       (v.z - m) * rinv * lw.z + lb.z,
                       (v.w - m) * rinv * lw.w + lb.w);
}

// One warp per node: f32 gather (unroll-2), SIR dynamics, 3x LN with six
// interleaved moment reductions, tail copy. Resets g_cnt for next run.
__global__ __launch_bounds__(256) void k_fused(
    const float* __restrict__ x, const float* __restrict__ lnw,
    const float* __restrict__ lnb, float* __restrict__ out, int n) {
    int warp = threadIdx.x >> 5, lane = threadIdx.x & 31;
    int i = blockIdx.x * 8 + warp;
    if (i >= n) return;

    const float4* h4 = (const float4*)g_h;
    const float4* x4 = (const float4*)x;
    float4* o4 = (float4*)out;

    float4 S = __ldcs(&h4[(size_t)i * 32 + lane]);
    float4 I = h4[((size_t)n + i) * 32 + lane];
    float4 X = __ldcs(&x4[((size_t)3 * n + i) * 32 + lane]);
    float beta = __shfl_sync(0xffffffffu, X.x, 0);
    float gam  = __shfl_sync(0xffffffffu, X.y, 0);

    int deg = min(g_cnt[i], CAP);
    if (lane == 0) g_cnt[i] = 0;                 // restore invariant for next run
    int c = (lane < deg) ? g_csr[(size_t)i * CAP + lane] : 0;

    float4 A0 = make_float4(0.f, 0.f, 0.f, 0.f);
    float4 A1 = make_float4(0.f, 0.f, 0.f, 0.f);
    int j = 0;
    for (; j + 2 <= deg; j += 2) {
        int c0 = __shfl_sync(0xffffffffu, c, j);
        int c1 = __shfl_sync(0xffffffffu, c, j + 1);
        float4 v0 = h4[((size_t)n + c0) * 32 + lane];
        float4 v1 = h4[((size_t)n + c1) * 32 + lane];
        A0.x += v0.x; A0.y += v0.y; A0.z += v0.z; A0.w += v0.w;
        A1.x += v1.x; A1.y += v1.y; A1.z += v1.z; A1.w += v1.w;
    }
    if (j < deg) {
        int c0 = __shfl_sync(0xffffffffu, c, j);
        float4 v0 = h4[((size_t)n + c0) * 32 + lane];
        A0.x += v0.x; A0.y += v0.y; A0.z += v0.z; A0.w += v0.w;
    }
    float4 AI = make_float4(A0.x + A1.x, A0.y + A1.y, A0.z + A1.z, A0.w + A1.w);

    float4 dS = make_float4(-beta * AI.x * S.x, -beta * AI.y * S.y,
                            -beta * AI.z * S.z, -beta * AI.w * S.w);
    float4 dI = make_float4(-dS.x - gam * I.x, -dS.y - gam * I.y,
                            -dS.z - gam * I.z, -dS.w - gam * I.w);
    float4 dR = make_float4(gam * I.x, gam * I.y, gam * I.z, gam * I.w);

    float sa1 = (dS.x + dS.y) + (dS.z + dS.w);
    float sa2 = (dS.x * dS.x + dS.y * dS.y) + (dS.z * dS.z + dS.w * dS.w);
    float sb1 = (dI.x + dI.y) + (dI.z + dI.w);
    float sb2 = (dI.x * dI.x + dI.y * dI.y) + (dI.z * dI.z + dI.w * dI.w);
    float sc1 = (dR.x + dR.y) + (dR.z + dR.w);
    float sc2 = (dR.x * dR.x + dR.y * dR.y) + (dR.z * dR.z + dR.w * dR.w);
#pragma unroll
    for (int o = 16; o; o >>= 1) {
        sa1 += __shfl_xor_sync(0xffffffffu, sa1, o);
        sa2 += __shfl_xor_sync(0xffffffffu, sa2, o);
        sb1 += __shfl_xor_sync(0xffffffffu, sb1, o);
        sb2 += __shfl_xor_sync(0xffffffffu, sb2, o);
        sc1 += __shfl_xor_sync(0xffffffffu, sc1, o);
        sc2 += __shfl_xor_sync(0xffffffffu, sc2, o);
    }
    float ma = sa1 * (1.f / 128.f), mb = sb1 * (1.f / 128.f), mc = sc1 * (1.f / 128.f);
    float ra = rsqrtf(fmaxf(sa2 * (1.f / 128.f) - ma * ma, 0.f) + 1e-5f);
    float rb = rsqrtf(fmaxf(sb2 * (1.f / 128.f) - mb * mb, 0.f) + 1e-5f);
    float rc = rsqrtf(fmaxf(sc2 * (1.f / 128.f) - mc * mc, 0.f) + 1e-5f);

    float4 lw = __ldg((const float4*)lnw + lane);
    float4 lb = __ldg((const float4*)lnb + lane);

    __stcs(&o4[(size_t)i * 32 + lane],           ln_apply(dS, ma, ra, lw, lb));
    __stcs(&o4[((size_t)n + i) * 32 + lane],     ln_apply(dI, mb, rb, lw, lb));
    __stcs(&o4[((size_t)2 * n + i) * 32 + lane], ln_apply(dR, mc, rc, lw, lb));
    __stcs(&o4[((size_t)3 * n + i) * 32 + lane], X);
}

extern "C" void kernel_launch(void* const* d_in, const int* in_sizes, int n_in,
                              void* d_out, int out_size) {
    // inputs: t, x, edge_row, edge_col, W, b, ln_w, ln_b (t unused)
    const float* x   = (const float*)d_in[1];
    const int*   er  = (const int*)d_in[2];
    const int*   ec  = (const int*)d_in[3];
    const float* W   = (const float*)d_in[4];
    const float* b   = (const float*)d_in[5];
    const float* lnw = (const float*)d_in[6];
    const float* lnb = (const float*)d_in[7];
    float* out = (float*)d_out;

    int n = (in_sizes[1] / HID) / 4;
    int E = in_sizes[2];
    int M = 2 * n;  // only S and I rows of h are ever used

    const int SMEM = 64 * WSH * 2;   // 18.4 KB fp16 W half
    cudaFuncSetAttribute(k_gemm_fill, cudaFuncAttributeMaxDynamicSharedMemorySize, SMEM);
    k_gemm_fill<<<NCTA, 256, SMEM>>>(x, W, b, M, er, ec, E, n);

    k_fused<<<(n + 7) / 8, 256>>>(x, lnw, lnb, out, n);
}